// round 13
// baseline (speedup 1.0000x reference)
#include <cuda_runtime.h>
#include <cuda_fp16.h>
#include <math.h>

// B=4, C=2, H=W=1024, DS=4 -> 256x256, NUM_SEEDS=32, 15 steps, pool 7x7.
// Register-resident flood: lane = row, 49 half2 regs = cols 0..97.
#define NCH   128
#define NREG  49
#define VROWB 208                 // bytes per exchanged row (13 uint4)
#define VBUF  (104 * VROWB)       // one v-exchange buffer
#define GOFF  (2 * VBUF)
#define GBUF  (104 * 16)
#define SMEM_BYTES (2 * VBUF + 2 * GBUF)

__device__ __half   g_road[4 * 256 * 256];
__device__ unsigned g_gtb[4 * 256 * 8];
__device__ int   g_sr[NCH];
__device__ int   g_sc[NCH];
__device__ int   g_scnt[NCH];
__device__ float g_sv[NCH];
__device__ float g_partial[NCH];
__device__ int   g_done;

__global__ void k_prep(const float* __restrict__ cls, const int* __restrict__ lab,
                       const float4* __restrict__ seeds) {
    if (blockIdx.x < 1024) {
        int idx = blockIdx.x * 256 + threadIdx.x;
        int j = idx & 255, i = (idx >> 8) & 255, b = idx >> 16;
        const float* c0 = cls + (size_t)(b * 2 + 0) * 1048576;
        const float* c1 = cls + (size_t)(b * 2 + 1) * 1048576;
        int r1 = 4 * i + 1, r2 = 4 * i + 2, cc = 4 * j;
        float4 a0 = *(const float4*)(c0 + r1 * 1024 + cc);
        float4 a1 = *(const float4*)(c1 + r1 * 1024 + cc);
        float4 b0 = *(const float4*)(c0 + r2 * 1024 + cc);
        float4 b1 = *(const float4*)(c1 + r2 * 1024 + cc);
        float p1 = 1.f / (1.f + expf(a0.y - a1.y));
        float p2 = 1.f / (1.f + expf(a0.z - a1.z));
        float p3 = 1.f / (1.f + expf(b0.y - b1.y));
        float p4 = 1.f / (1.f + expf(b0.z - b1.z));
        g_road[idx] = __float2half(0.25f * (p1 + p2 + p3 + p4));
        int g = lab[((size_t)b * 1024 + 4 * i) * 1024 + 4 * j];
        unsigned bits = __ballot_sync(0xffffffffu, g != 0);
        if ((threadIdx.x & 31) == 0)
            g_gtb[((size_t)b * 256 + i) * 8 + (j >> 5)] = bits;
    }
    {
        const unsigned n4 = (4 * 32 * 256 * 256) / 4;
        for (unsigned i = blockIdx.x * 256u + threadIdx.x; i < n4; i += 2048u * 256u) {
            float4 v = seeds[i];
            if (v.x > 0.f || v.y > 0.f || v.z > 0.f || v.w > 0.f) {
                float vals[4] = {v.x, v.y, v.z, v.w};
                #pragma unroll
                for (int k = 0; k < 4; k++) if (vals[k] > 0.f) {
                    unsigned idx = i * 4u + k;
                    int ch = idx >> 16;
                    g_sr[ch] = (idx >> 8) & 255;
                    g_sc[ch] = idx & 255;
                    g_sv[ch] = vals[k];
                    g_scnt[ch] = 1;
                }
            }
        }
    }
    asm volatile("griddepcontrol.launch_dependents;" ::: "memory");
}

__device__ __forceinline__ unsigned getword(const unsigned* row, int start) {
    int w = start >> 5;
    int sh = start & 31;
    unsigned lo = ((unsigned)w < 8u) ? row[w] : 0u;
    unsigned hi = ((unsigned)(w + 1) < 8u) ? row[w + 1] : 0u;
    return __funnelshift_r(lo, hi, sh);
}
__device__ __forceinline__ uint4 bshl(uint4 v, int s) {
    return make_uint4(v.x << s, __funnelshift_l(v.x, v.y, s),
                      __funnelshift_l(v.y, v.z, s), __funnelshift_l(v.z, v.w, s));
}
__device__ __forceinline__ uint4 bshr(uint4 v, int s) {
    return make_uint4(__funnelshift_r(v.x, v.y, s), __funnelshift_r(v.y, v.z, s),
                      __funnelshift_r(v.z, v.w, s), v.w >> s);
}
__device__ __forceinline__ uint4 bor(uint4 a, uint4 b) {
    return make_uint4(a.x | b.x, a.y | b.y, a.z | b.z, a.w | b.w);
}
__device__ __forceinline__ unsigned hmax2u(unsigned a, unsigned b) {
    __half2 r = __hmax2(*(__half2*)&a, *(__half2*)&b);
    return *(unsigned*)&r;
}
__device__ __forceinline__ unsigned hmin2u(unsigned a, unsigned b) {
    __half2 r = __hmin2(*(__half2*)&a, *(__half2*)&b);
    return *(unsigned*)&r;
}
#define FSR(a, b) __funnelshift_r((a), (b), 16)

// 128 threads: warp w, lane l -> row 26w + l - 3. Owned rows: lanes 3..28.
__global__ void __launch_bounds__(128, 1) k_flood(float* __restrict__ out) {
    extern __shared__ char sm[];
    __shared__ float wpart[4];
    __shared__ int   s_last;

    unsigned tid = threadIdx.x;
    int w = tid >> 5, l = tid & 31;
    int rr = 26 * w + l - 3;              // this lane's row (-3..103)
    int ch = blockIdx.x, b = ch >> 5;
    const float c0log = -logf(1.0f - 1e-7f);

    // pre-dependency: zero staging buffer (v-buffer 1) while k_prep drains
    {
        uint4 z = make_uint4(0, 0, 0, 0);
        uint4* p = (uint4*)(sm + VBUF);
        for (int i = tid; i < VBUF / 16; i += 128) p[i] = z;
    }
    asm volatile("griddepcontrol.wait;" ::: "memory");
    __syncthreads();

    bool hasseed = (g_scnt[ch] != 0);
    if (hasseed) {
        int sr = g_sr[ch], sc = g_sc[ch];
        float sv = g_sv[ch];
        int gr0 = sr - 48, gc0 = sc - 48;

        // ---- fill staging (v-buffer 1) with mask crop ----
        for (unsigned idx = tid; idx < 97u * 97u; idx += 128) {
            unsigned y = idx / 97u;
            unsigned x = idx - y * 97u;
            int gy = gr0 + (int)y, gx = gc0 + (int)x;
            __half mv = __ushort_as_half((unsigned short)0);
            if ((unsigned)gy < 256u && (unsigned)gx < 256u)
                mv = g_road[(b << 16) + (gy << 8) + gx];
            *(__half*)(sm + VBUF + y * VROWB + x * 2) = mv;
        }
        __syncthreads();

        // ---- per-lane registers ----
        unsigned v[NREG], m[NREG];
        #pragma unroll
        for (int k = 0; k < NREG; k++) v[k] = 0u;
        if (rr >= 0) {                         // rr <= 103 always
            const char* src = sm + VBUF + rr * VROWB;
            #pragma unroll
            for (int k = 0; k < NREG; k++) m[k] = *(const unsigned*)(src + k * 4);
        } else {
            #pragma unroll
            for (int k = 0; k < NREG; k++) m[k] = 0u;
        }
        uint4 grow = make_uint4(0, 0, 0, 0);
        uint4 gmask = make_uint4(0, 0, 0, 0);
        if (rr >= 0 && rr <= 96) {
            int gy = gr0 + rr;
            if ((unsigned)gy < 256u) {
                const unsigned* row = &g_gtb[((size_t)b * 256 + gy) * 8];
                gmask.x = getword(row, gc0);
                gmask.y = getword(row, gc0 + 32);
                gmask.z = getword(row, gc0 + 64);
                gmask.w = getword(row, gc0 + 96) & 1u;
            }
        }
        unsigned seedlo = (unsigned)__half_as_ushort(__float2half(sv));
        if (tid == 57) {                       // warp 1 lane 25 = row 48
            v[24] = hmax2u(v[24], seedlo);     // col 48 = reg 24 lo
            grow.y |= (1u << 16);
        }

        int wlo = 26 * w - 3, whi = 26 * w + 28;

        #pragma unroll 1
        for (int it = 0; it < 15; it++) {
            int R = 3 * (it + 1);
            bool wact = (whi >= 45 - R) && (wlo <= 51 + R);
            if (wact) {
                // ---- horizontal 7-max, in-register ----
                unsigned a[51];
                #pragma unroll
                for (int k = 0; k < 51; k++) {
                    unsigned vk  = (k < NREG) ? v[k] : 0u;
                    unsigned vk1 = (k + 1 < NREG) ? v[k + 1] : 0u;
                    a[k] = hmax2u(vk, FSR(vk, vk1));
                }
                unsigned bb[51];
                #pragma unroll
                for (int k = 0; k < 51; k++)
                    bb[k] = hmax2u(a[k], (k + 1 < 51) ? a[k + 1] : 0u);
                // left-edge virtual bb[-1], bb[-2]
                unsigned col0 = v[0] & 0xFFFFu;
                unsigned a0lo = a[0] & 0xFFFFu;             // b4(-2) = max cols 0..1
                unsigned col2 = v[1] & 0xFFFFu;
                unsigned b4m1 = hmax2u(a0lo, col2) & 0xFFFFu; // b4(-1) = max cols 0..2
                unsigned bbm1 = a0lo | (b4m1 << 16);
                unsigned bbm2 = col0 << 16;                  // (0, b4(-3)=col0)
                unsigned h[NREG];
                #pragma unroll
                for (int k = 0; k < NREG; k++) {
                    unsigned bm2 = (k >= 2) ? bb[k - 2] : (k == 1 ? bbm1 : bbm2);
                    unsigned bm1 = (k >= 1) ? bb[k - 1] : bbm1;
                    h[k] = hmax2u(FSR(bm2, bm1), bb[k]);
                }
                // ---- vertical 7-max (intra-warp shuffles) + min(mask) ----
                #pragma unroll
                for (int k = 0; k < NREG; k++) {
                    unsigned p  = hmax2u(h[k], __shfl_down_sync(0xffffffffu, h[k], 1));
                    unsigned b4 = hmax2u(p,   __shfl_down_sync(0xffffffffu, p, 2));
                    unsigned o  = hmax2u(b4,  __shfl_up_sync(0xffffffffu, b4, 3));
                    v[k] = hmin2u(o, m[k]);
                }
                if (tid == 57) v[24] = hmax2u(v[24], seedlo);
            }
            // ---- gt bitwise flood (always; cheap) ----
            {
                uint4 gh = bor(grow, bor(bshl(grow, 1), bshr(grow, 1)));
                gh = bor(gh, bor(bshl(grow, 2), bshr(grow, 2)));
                gh = bor(gh, bor(bshl(grow, 3), bshr(grow, 3)));
                uint4 p, b4, o;
                p.x = gh.x | __shfl_down_sync(0xffffffffu, gh.x, 1);
                p.y = gh.y | __shfl_down_sync(0xffffffffu, gh.y, 1);
                p.z = gh.z | __shfl_down_sync(0xffffffffu, gh.z, 1);
                p.w = gh.w | __shfl_down_sync(0xffffffffu, gh.w, 1);
                b4.x = p.x | __shfl_down_sync(0xffffffffu, p.x, 2);
                b4.y = p.y | __shfl_down_sync(0xffffffffu, p.y, 2);
                b4.z = p.z | __shfl_down_sync(0xffffffffu, p.z, 2);
                b4.w = p.w | __shfl_down_sync(0xffffffffu, p.w, 2);
                o.x = b4.x | __shfl_up_sync(0xffffffffu, b4.x, 3);
                o.y = b4.y | __shfl_up_sync(0xffffffffu, b4.y, 3);
                o.z = b4.z | __shfl_up_sync(0xffffffffu, b4.z, 3);
                o.w = b4.w | __shfl_up_sync(0xffffffffu, b4.w, 3);
                grow.x = o.x & gmask.x;
                grow.y = o.y & gmask.y;
                grow.z = o.z & gmask.z;
                grow.w = o.w & gmask.w;
                if (tid == 57) grow.y |= (1u << 16);
            }
            // ---- halo exchange (double-buffered, one barrier) ----
            char* vb = sm + (it & 1) * VBUF;
            char* gb = sm + GOFF + (it & 1) * GBUF;
            if ((l >= 3 && l <= 5) || (l >= 26 && l <= 28)) {
                uint4* dst = (uint4*)(vb + rr * VROWB);
                #pragma unroll
                for (int q = 0; q < 12; q++)
                    dst[q] = make_uint4(v[4 * q], v[4 * q + 1], v[4 * q + 2], v[4 * q + 3]);
                *(unsigned*)(vb + rr * VROWB + 192) = v[48];
                *(uint4*)(gb + rr * 16) = grow;
            }
            __syncthreads();
            if ((l <= 2 && w > 0) || (l >= 29 && w < 3)) {
                const uint4* src = (const uint4*)(vb + rr * VROWB);
                #pragma unroll
                for (int q = 0; q < 12; q++) {
                    uint4 t = src[q];
                    v[4 * q] = t.x; v[4 * q + 1] = t.y; v[4 * q + 2] = t.z; v[4 * q + 3] = t.w;
                }
                v[48] = *(const unsigned*)(vb + rr * VROWB + 192);
                grow = *(const uint4*)(gb + rr * 16);
            }
        }

        // ---- BCE from registers ----
        int ylo = 3 > -gr0 ? 3 : -gr0;
        int yhi = 93 < 255 - gr0 ? 93 : 255 - gr0;
        int xlo = 3 > -gc0 ? 3 : -gc0;
        int xhi = 93 < 255 - gc0 ? 93 : 255 - gc0;
        float pm = 1.0f;
        int   pe = 0;
        if (l >= 3 && l <= 28 && rr >= ylo && rr <= yhi) {
            #pragma unroll
            for (int k = 0; k < NREG; k++) {
                const int c0 = 2 * k, c1 = 2 * k + 1;
                if (c1 < xlo || c0 > xhi) continue;   // runtime; cheap
                float2 f = __half22float2(*(__half2*)&v[k]);
                const int w0i = c0 >> 5, w1i = c1 >> 5;
                unsigned word0 = w0i == 0 ? grow.x : w0i == 1 ? grow.y : w0i == 2 ? grow.z : grow.w;
                unsigned word1 = w1i == 0 ? grow.x : w1i == 1 ? grow.y : w1i == 2 ? grow.z : grow.w;
                if (c0 >= xlo && c0 <= xhi) {
                    float p = fminf(fmaxf(f.x, 1e-7f), 1.0f - 1e-7f);
                    pm *= ((word0 >> (c0 & 31)) & 1u) ? p : (1.0f - p);
                }
                if (c1 >= xlo && c1 <= xhi) {
                    float p = fminf(fmaxf(f.y, 1e-7f), 1.0f - 1e-7f);
                    pm *= ((word1 >> (c1 & 31)) & 1u) ? p : (1.0f - p);
                }
                int bi = __float_as_int(pm);
                pe += (bi >> 23) - 127;
                pm = __int_as_float((bi & 0x007fffff) | 0x3f800000);
            }
        }
        float local = -(__logf(pm) + (float)pe * 0.69314718056f);
        #pragma unroll
        for (int off = 16; off; off >>= 1)
            local += __shfl_down_sync(0xffffffffu, local, off);
        if (l == 0) wpart[w] = local;
        __syncthreads();
        if (tid == 0) {
            float s = wpart[0] + wpart[1] + wpart[2] + wpart[3];
            float area = (float)((yhi - ylo + 1) * (xhi - xlo + 1));
            s += (65536.0f - area) * c0log;
            g_partial[ch] = s;
        }
    } else {
        if (tid == 0) g_partial[ch] = 65536.0f * c0log;
    }

    // ---- last-block finalize ----
    if (tid == 0) {
        __threadfence();
        int old = atomicAdd(&g_done, 1);
        s_last = (old == NCH - 1);
    }
    __syncthreads();
    if (s_last && tid < 32) {
        float fv = g_partial[tid] + g_partial[tid + 32] +
                   g_partial[tid + 64] + g_partial[tid + 96];
        #pragma unroll
        for (int off = 16; off; off >>= 1)
            fv += __shfl_down_sync(0xffffffffu, fv, off);
        if (tid == 0) {
            out[0] = 0.5f * fv / 8388608.0f;
            g_done = 0;
        }
    }
}

extern "C" void kernel_launch(void* const* d_in, const int* in_sizes, int n_in,
                              void* d_out, int out_size) {
    const float* cls = (const float*)d_in[0];
    const int* lab   = (const int*)d_in[1];
    const float4* seeds = (const float4*)d_in[2];

    cudaFuncSetAttribute(k_flood, cudaFuncAttributeMaxDynamicSharedMemorySize, SMEM_BYTES);

    k_prep<<<2048, 256>>>(cls, lab, seeds);

    cudaLaunchConfig_t cfg = {};
    cfg.gridDim = dim3(128, 1, 1);
    cfg.blockDim = dim3(128, 1, 1);
    cfg.dynamicSmemBytes = SMEM_BYTES;
    cfg.stream = 0;
    cudaLaunchAttribute attr[1];
    attr[0].id = cudaLaunchAttributeProgrammaticStreamSerialization;
    attr[0].val.programmaticStreamSerializationAllowed = 1;
    cfg.attrs = attr;
    cfg.numAttrs = 1;
    float* outp = (float*)d_out;
    cudaError_t e = cudaLaunchKernelEx(&cfg, k_flood, outp);
    if (e != cudaSuccess) {
        k_flood<<<128, 128, SMEM_BYTES>>>(outp);
    }
}